// round 15
// baseline (speedup 1.0000x reference)
#include <cuda_runtime.h>
#include <cstdint>

// Problem constants (fixed by the reference: B=4, C=8, H=W=1024, R=1 cross kernel, wrap pad)
constexpr int Hh = 1024;
constexpr int Ww = 1024;
constexpr int PLANE = Hh * Ww;          // 1,048,576
constexpr int SPB = 114;                // strips per batch: 4*114 = 456 CTAs = 3/SM x 152 SMs

// Accurate fp32 exp (Cody-Waite reduction + cephes degree-6 poly, ~1 ulp).
__device__ __forceinline__ float exp_acc(float x) {
    x = fminf(fmaxf(x, -87.3f), 88.0f);
    float n = rintf(x * 1.44269504088896341f);
    float r = fmaf(n, -0.693359375f, x);        // Cody-Waite hi
    r = fmaf(n, 2.12194440e-4f, r);             // Cody-Waite lo
    float rr = r * r;
    float y = 1.9875691500e-4f;
    y = fmaf(y, r, 1.3981999507e-3f);
    y = fmaf(y, r, 8.3334519073e-3f);
    y = fmaf(y, r, 4.1665795894e-2f);
    y = fmaf(y, r, 1.6666665459e-1f);
    y = fmaf(y, r, 5.0000001201e-1f);
    y = fmaf(y, rr, r);
    y = y + 1.0f;
    float sc = __int_as_float(((int)n + 127) << 23);
    return y * sc;
}

__device__ __forceinline__ float flip_one(float s, float J, float bf, float r, bool drop) {
    float de = 2.0f * s * J;
    bool flip;
    if (de <= 0.0f) {
        flip = drop;                            // p = 1, rand in [0,1) < 1 always
    } else {
        float p = exp_acc(-de * bf);
        flip = (r < p) && drop;
    }
    return flip ? -s : s;
}

__device__ __forceinline__ float4 ld4(const float* p) {
    return *reinterpret_cast<const float4*>(p);
}
__device__ __forceinline__ float4 ld_cs4(const float* p) {
    return __ldcs(reinterpret_cast<const float4*>(p));
}
__device__ __forceinline__ void st_cs4(float* p, float4 v) {
    __stcs(reinterpret_cast<float4*>(p), v);
}

// J(h,w) = S(h-1,w)+S(h+1,w)+S(h,w-1)+S(h,w+1), S = sum_c s_c (cross kernel,
// one output channel). 512-thread CTAs: half A owns row hc, half B row hc+1,
// 2 rows per iteration with ONE barrier. Grid = 4 x 114 = 456 CTAs = exactly
// 3 per SM (balanced single wave, 48 warps/SM — the occupancy probe vs R14's
// 32). Body identical to R14; only residency changed.
__global__ __launch_bounds__(512, 3) void ising_step_kernel(
    const float* __restrict__ x,      // (4, 9, 1024, 1024): s = ch 0..7, b = ch 8
    const float* __restrict__ rnd,    // (4, 8, 1024, 1024)
    const float* __restrict__ drop,   // (1024, 1024)
    float* __restrict__ out)          // (4, 9, 1024, 1024)
{
    __shared__ float S[6][Ww];        // S row (h_start-1+j) lives in slot j%6

    int b     = blockIdx.x / SPB;
    int strip = blockIdx.x - b * SPB;
    int h_start = (strip * Hh) / SPB;
    int h_end   = ((strip + 1) * Hh) / SPB;      // 8 or 9 rows
    int half = threadIdx.x >> 8;                 // 0: row hc, 1: row hc+1
    int t    = threadIdx.x & 255;
    int w    = t * 4;
    int wl   = (w + Ww - 1) & (Ww - 1);          // left-of-pixel-0 (row wrap, in-block)
    int wr   = (w + 4) & (Ww - 1);               // right-of-pixel-3

    const float* xb = x + b * 9 * PLANE;
    const float* rb = rnd + b * 8 * PLANE;
    float* ob = out + b * 9 * PLANE;

    // Prologue: half A -> S(h_start-1) slot 0, half B -> S(h_start) slot 1.
    // Visibility is covered by the first in-loop barrier.
    {
        int h = (h_start + Hh - 1 + half) & (Hh - 1);
        const float* sp = xb + h * Ww + w;
        float4 cv[8];
        #pragma unroll
        for (int c = 0; c < 8; c++) cv[c] = ld4(sp + c * PLANE);
        float4 s4 = make_float4(0.f, 0.f, 0.f, 0.f);
        #pragma unroll
        for (int c = 0; c < 8; c++) {
            s4.x += cv[c].x; s4.y += cv[c].y; s4.z += cv[c].z; s4.w += cv[c].w;
        }
        *reinterpret_cast<float4*>(&S[half][w]) = s4;
    }

    int n = h_end - h_start;
    int npairs = (n + 1) >> 1;

    #pragma unroll 1
    for (int k = 0; k < npairs; k++) {
        // ---- Phase 1: each half loads one new S row (local j = 2+2k+half) ----
        {
            int hl = (h_start + 1 + 2 * k + half) & (Hh - 1);
            int slot = (2 + 2 * k + half) % 6;
            const float* sp = xb + hl * Ww + w;
            float4 cv[8];
            #pragma unroll
            for (int c = 0; c < 8; c++) cv[c] = ld4(sp + c * PLANE);
            float4 s4 = make_float4(0.f, 0.f, 0.f, 0.f);
            #pragma unroll
            for (int c = 0; c < 8; c++) {
                s4.x += cv[c].x; s4.y += cv[c].y; s4.z += cv[c].z; s4.w += cv[c].w;
            }
            *reinterpret_cast<float4*>(&S[slot][w]) = s4;
        }
        __syncthreads();                         // one barrier per TWO output rows

        // ---- Phases 2+3: my output row hc = h_start + 2k + half ----
        int hc = h_start + 2 * k + half;
        if (hc < h_end) {                        // odd-n tail: half B idles (post-barrier: safe)
            int jc = 1 + 2 * k + half;           // local index of row hc
            const float* Su = S[(jc - 1) % 6];   // S(hc-1)
            const float* Sc = S[jc % 6];         // S(hc)
            const float* Sd = S[(jc + 1) % 6];   // S(hc+1)
            float4 su = *reinterpret_cast<const float4*>(&Su[w]);
            float4 sc = *reinterpret_cast<const float4*>(&Sc[w]);
            float4 sd = *reinterpret_cast<const float4*>(&Sd[w]);
            float lf = Sc[wl], rt = Sc[wr];
            float4 J;
            J.x = (su.x + sd.x) + (lf   + sc.y);
            J.y = (su.y + sd.y) + (sc.x + sc.z);
            J.z = (su.z + sd.z) + (sc.y + sc.w);
            J.w = (su.w + sd.w) + (sc.z + rt);

            int rowc = hc * Ww + w;
            float4 bf = ld4(xb + 8 * PLANE + rowc);
            float4 dv = ld4(drop + rowc);
            bool d0 = dv.x > 0.5f, d1 = dv.y > 0.5f, d2 = dv.z > 0.5f, d3 = dv.w > 0.5f;
            st_cs4(ob + 8 * PLANE + rowc, bf);   // pass-through field (write-once)

            #pragma unroll
            for (int c = 0; c < 8; c++) {
                float4 cc = ld4(xb + c * PLANE + rowc);    // staged this/last iter -> cache hit
                float4 rv = ld_cs4(rb + c * PLANE + rowc); // read-once stream
                float4 o;
                o.x = flip_one(cc.x, J.x, bf.x, rv.x, d0);
                o.y = flip_one(cc.y, J.y, bf.y, rv.y, d1);
                o.z = flip_one(cc.z, J.z, bf.z, rv.z, d2);
                o.w = flip_one(cc.w, J.w, bf.w, rv.w, d3);
                st_cs4(ob + c * PLANE + rowc, o);          // write-once
            }
        }
    }
}

extern "C" void kernel_launch(void* const* d_in, const int* in_sizes, int n_in,
                              void* d_out, int out_size) {
    const float* x    = (const float*)d_in[0];   // (4,9,1024,1024)
    const float* rnd  = (const float*)d_in[1];   // (4,8,1024,1024)
    const float* drop = (const float*)d_in[2];   // (1024,1024)
    // d_in[3] = nn_kernel: fixed cross structure, baked into the kernel
    float* out = (float*)d_out;

    int grid = 4 * SPB;                          // 456 CTAs = 3/SM x 152 SMs, single wave
    ising_step_kernel<<<grid, 512>>>(x, rnd, drop, out);
}

// round 16
// speedup vs baseline: 1.0037x; 1.0037x over previous
#include <cuda_runtime.h>
#include <cstdint>

// Problem constants (fixed by the reference: B=4, C=8, H=W=1024, R=1 cross kernel, wrap pad)
constexpr int Hh = 1024;
constexpr int Ww = 1024;
constexpr int PLANE = Hh * Ww;          // 1,048,576
constexpr int SPB = 76;                 // strips per batch: 4*76 = 304 CTAs = 2/SM x 152 SMs

// Accurate fp32 exp (Cody-Waite reduction + cephes degree-6 poly, ~1 ulp).
__device__ __forceinline__ float exp_acc(float x) {
    x = fminf(fmaxf(x, -87.3f), 88.0f);
    float n = rintf(x * 1.44269504088896341f);
    float r = fmaf(n, -0.693359375f, x);        // Cody-Waite hi
    r = fmaf(n, 2.12194440e-4f, r);             // Cody-Waite lo
    float rr = r * r;
    float y = 1.9875691500e-4f;
    y = fmaf(y, r, 1.3981999507e-3f);
    y = fmaf(y, r, 8.3334519073e-3f);
    y = fmaf(y, r, 4.1665795894e-2f);
    y = fmaf(y, r, 1.6666665459e-1f);
    y = fmaf(y, r, 5.0000001201e-1f);
    y = fmaf(y, rr, r);
    y = y + 1.0f;
    float sc = __int_as_float(((int)n + 127) << 23);
    return y * sc;
}

__device__ __forceinline__ float flip_one(float s, float J, float bf, float r, bool drop) {
    float de = 2.0f * s * J;
    bool flip;
    if (de <= 0.0f) {
        flip = drop;                            // p = 1, rand in [0,1) < 1 always
    } else {
        float p = exp_acc(-de * bf);
        flip = (r < p) && drop;
    }
    return flip ? -s : s;
}

__device__ __forceinline__ float4 ld4(const float* p) {
    return *reinterpret_cast<const float4*>(p);
}
__device__ __forceinline__ float4 ld_cs4(const float* p) {
    return __ldcs(reinterpret_cast<const float4*>(p));
}
__device__ __forceinline__ void st_cs4(float* p, float4 v) {
    __stcs(reinterpret_cast<float4*>(p), v);
}

// J(h,w) = S(h-1,w)+S(h+1,w)+S(h,w-1)+S(h,w+1), S = sum_c s_c (cross kernel,
// one output channel). 512-thread CTAs: half A owns row hc, half B row hc+1,
// 2 rows per iteration with ONE barrier. Grid = 4 x 76 = 304 CTAs = exactly
// 2 per SM (balanced single wave; R14 champion config). R16 change: the
// row-local work that does NOT depend on S (bf load, drop load, masks, field
// pass-through store) is hoisted ABOVE the barrier into the phase-1 miss
// batch, deepening per-warp MLP and shortening the post-barrier path.
__global__ __launch_bounds__(512, 2) void ising_step_kernel(
    const float* __restrict__ x,      // (4, 9, 1024, 1024): s = ch 0..7, b = ch 8
    const float* __restrict__ rnd,    // (4, 8, 1024, 1024)
    const float* __restrict__ drop,   // (1024, 1024)
    float* __restrict__ out)          // (4, 9, 1024, 1024)
{
    __shared__ float S[6][Ww];        // S row (h_start-1+j) lives in slot j%6

    int b     = blockIdx.x / SPB;
    int strip = blockIdx.x - b * SPB;
    int h_start = (strip * Hh) / SPB;
    int h_end   = ((strip + 1) * Hh) / SPB;      // 13 or 14 rows
    int half = threadIdx.x >> 8;                 // 0: row hc, 1: row hc+1
    int t    = threadIdx.x & 255;
    int w    = t * 4;
    int wl   = (w + Ww - 1) & (Ww - 1);          // left-of-pixel-0 (row wrap, in-block)
    int wr   = (w + 4) & (Ww - 1);               // right-of-pixel-3

    const float* xb = x + b * 9 * PLANE;
    const float* rb = rnd + b * 8 * PLANE;
    float* ob = out + b * 9 * PLANE;

    // Prologue: half A -> S(h_start-1) slot 0, half B -> S(h_start) slot 1.
    // Visibility is covered by the first in-loop barrier.
    {
        int h = (h_start + Hh - 1 + half) & (Hh - 1);
        const float* sp = xb + h * Ww + w;
        float4 cv[8];
        #pragma unroll
        for (int c = 0; c < 8; c++) cv[c] = ld4(sp + c * PLANE);
        float4 s4 = make_float4(0.f, 0.f, 0.f, 0.f);
        #pragma unroll
        for (int c = 0; c < 8; c++) {
            s4.x += cv[c].x; s4.y += cv[c].y; s4.z += cv[c].z; s4.w += cv[c].w;
        }
        *reinterpret_cast<float4*>(&S[half][w]) = s4;
    }

    int n = h_end - h_start;
    int npairs = (n + 1) >> 1;

    #pragma unroll 1
    for (int k = 0; k < npairs; k++) {
        int hc = h_start + 2 * k + half;         // my output row this iteration
        bool active = (hc < h_end);              // odd-n tail: half B idles on last iter
        int rowc = hc * Ww + w;

        // ---- Phase 0 (pre-barrier, S-independent): bf/drop loads, masks,
        //      field pass-through store. Overlaps the phase-1 miss batch. ----
        float4 bf = make_float4(0.f, 0.f, 0.f, 0.f);
        bool d0 = false, d1 = false, d2 = false, d3 = false;
        if (active) {
            bf = ld4(xb + 8 * PLANE + rowc);
            float4 dv = ld4(drop + rowc);
            d0 = dv.x > 0.5f; d1 = dv.y > 0.5f; d2 = dv.z > 0.5f; d3 = dv.w > 0.5f;
            st_cs4(ob + 8 * PLANE + rowc, bf);   // write-once pass-through
        }

        // ---- Phase 1: each half loads one new S row (local j = 2+2k+half) ----
        {
            int hl = (h_start + 1 + 2 * k + half) & (Hh - 1);
            int slot = (2 + 2 * k + half) % 6;
            const float* sp = xb + hl * Ww + w;
            float4 cv[8];
            #pragma unroll
            for (int c = 0; c < 8; c++) cv[c] = ld4(sp + c * PLANE);
            float4 s4 = make_float4(0.f, 0.f, 0.f, 0.f);
            #pragma unroll
            for (int c = 0; c < 8; c++) {
                s4.x += cv[c].x; s4.y += cv[c].y; s4.z += cv[c].z; s4.w += cv[c].w;
            }
            *reinterpret_cast<float4*>(&S[slot][w]) = s4;
        }
        __syncthreads();                         // one barrier per TWO output rows

        // ---- Phases 2+3: J + flips for my row ----
        if (active) {
            int jc = 1 + 2 * k + half;           // local index of row hc
            const float* Su = S[(jc - 1) % 6];   // S(hc-1)
            const float* Sc = S[jc % 6];         // S(hc)
            const float* Sd = S[(jc + 1) % 6];   // S(hc+1)
            float4 su = *reinterpret_cast<const float4*>(&Su[w]);
            float4 sc = *reinterpret_cast<const float4*>(&Sc[w]);
            float4 sd = *reinterpret_cast<const float4*>(&Sd[w]);
            float lf = Sc[wl], rt = Sc[wr];
            float4 J;
            J.x = (su.x + sd.x) + (lf   + sc.y);
            J.y = (su.y + sd.y) + (sc.x + sc.z);
            J.z = (su.z + sd.z) + (sc.y + sc.w);
            J.w = (su.w + sd.w) + (sc.z + rt);

            #pragma unroll
            for (int c = 0; c < 8; c++) {
                float4 cc = ld4(xb + c * PLANE + rowc);    // staged this/last iter -> cache hit
                float4 rv = ld_cs4(rb + c * PLANE + rowc); // read-once stream
                float4 o;
                o.x = flip_one(cc.x, J.x, bf.x, rv.x, d0);
                o.y = flip_one(cc.y, J.y, bf.y, rv.y, d1);
                o.z = flip_one(cc.z, J.z, bf.z, rv.z, d2);
                o.w = flip_one(cc.w, J.w, bf.w, rv.w, d3);
                st_cs4(ob + c * PLANE + rowc, o);          // write-once
            }
        }
    }
}

extern "C" void kernel_launch(void* const* d_in, const int* in_sizes, int n_in,
                              void* d_out, int out_size) {
    const float* x    = (const float*)d_in[0];   // (4,9,1024,1024)
    const float* rnd  = (const float*)d_in[1];   // (4,8,1024,1024)
    const float* drop = (const float*)d_in[2];   // (1024,1024)
    // d_in[3] = nn_kernel: fixed cross structure, baked into the kernel
    float* out = (float*)d_out;

    int grid = 4 * SPB;                          // 304 CTAs = 2/SM x 152 SMs, single wave
    ising_step_kernel<<<grid, 512>>>(x, rnd, drop, out);
}

// round 17
// speedup vs baseline: 1.0683x; 1.0643x over previous
#include <cuda_runtime.h>
#include <cstdint>

// Problem constants (fixed by the reference: B=4, C=8, H=W=1024, R=1 cross kernel, wrap pad)
constexpr int Hh = 1024;
constexpr int Ww = 1024;
constexpr int PLANE = Hh * Ww;          // 1,048,576
constexpr int SPB = 76;                 // strips per batch: 4*76 = 304 CTAs = 2/SM x 152 SMs

// Accurate fp32 exp (Cody-Waite reduction + cephes degree-6 poly, ~1 ulp).
__device__ __forceinline__ float exp_acc(float x) {
    x = fminf(fmaxf(x, -87.3f), 88.0f);
    float n = rintf(x * 1.44269504088896341f);
    float r = fmaf(n, -0.693359375f, x);        // Cody-Waite hi
    r = fmaf(n, 2.12194440e-4f, r);             // Cody-Waite lo
    float rr = r * r;
    float y = 1.9875691500e-4f;
    y = fmaf(y, r, 1.3981999507e-3f);
    y = fmaf(y, r, 8.3334519073e-3f);
    y = fmaf(y, r, 4.1665795894e-2f);
    y = fmaf(y, r, 1.6666665459e-1f);
    y = fmaf(y, r, 5.0000001201e-1f);
    y = fmaf(y, rr, r);
    y = y + 1.0f;
    float sc = __int_as_float(((int)n + 127) << 23);
    return y * sc;
}

__device__ __forceinline__ float flip_one(float s, float J, float bf, float r, bool drop) {
    float de = 2.0f * s * J;
    bool flip;
    if (de <= 0.0f) {
        flip = drop;                            // p = 1, rand in [0,1) < 1 always
    } else {
        float p = exp_acc(-de * bf);
        flip = (r < p) && drop;
    }
    return flip ? -s : s;
}

__device__ __forceinline__ float4 ld4(const float* p) {
    return *reinterpret_cast<const float4*>(p);
}
__device__ __forceinline__ float4 ld_cs4(const float* p) {
    return __ldcs(reinterpret_cast<const float4*>(p));
}
__device__ __forceinline__ void st_cs4(float* p, float4 v) {
    __stcs(reinterpret_cast<float4*>(p), v);
}

// J(h,w) = S(h-1,w)+S(h+1,w)+S(h,w-1)+S(h,w+1), S = sum_c s_c (cross kernel,
// one output channel). 512-thread CTAs: half A (warps 0-7) owns row hc, half B
// (warps 8-15) owns row hc+1, processing 2 rows per iteration with ONE barrier.
// Grid = 4 batches x 76 strips = 304 CTAs = exactly 2 per SM (balanced single
// wave). Strips of ~13.5 rows amortize the 2-row S prologue (s read factor
// 1.30 -> 1.15). 6-slot rolling S ring in smem (24 KB); outputs stored .cs
// (write-once, keep L2 for s-row reuse). Champion configuration (R14).
__global__ __launch_bounds__(512, 2) void ising_step_kernel(
    const float* __restrict__ x,      // (4, 9, 1024, 1024): s = ch 0..7, b = ch 8
    const float* __restrict__ rnd,    // (4, 8, 1024, 1024)
    const float* __restrict__ drop,   // (1024, 1024)
    float* __restrict__ out)          // (4, 9, 1024, 1024)
{
    __shared__ float S[6][Ww];        // S row (h_start-1+j) lives in slot j%6

    int b     = blockIdx.x / SPB;
    int strip = blockIdx.x - b * SPB;
    int h_start = (strip * Hh) / SPB;
    int h_end   = ((strip + 1) * Hh) / SPB;      // 13 or 14 rows
    int half = threadIdx.x >> 8;                 // 0: row hc, 1: row hc+1
    int t    = threadIdx.x & 255;
    int w    = t * 4;
    int wl   = (w + Ww - 1) & (Ww - 1);          // left-of-pixel-0 (row wrap, in-block)
    int wr   = (w + 4) & (Ww - 1);               // right-of-pixel-3

    const float* xb = x + b * 9 * PLANE;
    const float* rb = rnd + b * 8 * PLANE;
    float* ob = out + b * 9 * PLANE;

    // Prologue: half A -> S(h_start-1) slot 0, half B -> S(h_start) slot 1.
    // Visibility is covered by the first in-loop barrier.
    {
        int h = (h_start + Hh - 1 + half) & (Hh - 1);
        const float* sp = xb + h * Ww + w;
        float4 cv[8];
        #pragma unroll
        for (int c = 0; c < 8; c++) cv[c] = ld4(sp + c * PLANE);
        float4 s4 = make_float4(0.f, 0.f, 0.f, 0.f);
        #pragma unroll
        for (int c = 0; c < 8; c++) {
            s4.x += cv[c].x; s4.y += cv[c].y; s4.z += cv[c].z; s4.w += cv[c].w;
        }
        *reinterpret_cast<float4*>(&S[half][w]) = s4;
    }

    int n = h_end - h_start;
    int npairs = (n + 1) >> 1;

    #pragma unroll 1
    for (int k = 0; k < npairs; k++) {
        // ---- Phase 1: each half loads one new S row (local j = 2+2k+half) ----
        {
            int hl = (h_start + 1 + 2 * k + half) & (Hh - 1);
            int slot = (2 + 2 * k + half) % 6;
            const float* sp = xb + hl * Ww + w;
            float4 cv[8];
            #pragma unroll
            for (int c = 0; c < 8; c++) cv[c] = ld4(sp + c * PLANE);
            float4 s4 = make_float4(0.f, 0.f, 0.f, 0.f);
            #pragma unroll
            for (int c = 0; c < 8; c++) {
                s4.x += cv[c].x; s4.y += cv[c].y; s4.z += cv[c].z; s4.w += cv[c].w;
            }
            *reinterpret_cast<float4*>(&S[slot][w]) = s4;
        }
        __syncthreads();                         // one barrier per TWO output rows

        // ---- Phases 2+3: my output row hc = h_start + 2k + half ----
        int hc = h_start + 2 * k + half;
        if (hc < h_end) {                        // odd-n tail: half B idles (post-barrier: safe)
            int jc = 1 + 2 * k + half;           // local index of row hc
            const float* Su = S[(jc - 1) % 6];   // S(hc-1)
            const float* Sc = S[jc % 6];         // S(hc)
            const float* Sd = S[(jc + 1) % 6];   // S(hc+1)
            float4 su = *reinterpret_cast<const float4*>(&Su[w]);
            float4 sc = *reinterpret_cast<const float4*>(&Sc[w]);
            float4 sd = *reinterpret_cast<const float4*>(&Sd[w]);
            float lf = Sc[wl], rt = Sc[wr];
            float4 J;
            J.x = (su.x + sd.x) + (lf   + sc.y);
            J.y = (su.y + sd.y) + (sc.x + sc.z);
            J.z = (su.z + sd.z) + (sc.y + sc.w);
            J.w = (su.w + sd.w) + (sc.z + rt);

            int rowc = hc * Ww + w;
            float4 bf = ld4(xb + 8 * PLANE + rowc);
            float4 dv = ld4(drop + rowc);
            bool d0 = dv.x > 0.5f, d1 = dv.y > 0.5f, d2 = dv.z > 0.5f, d3 = dv.w > 0.5f;
            st_cs4(ob + 8 * PLANE + rowc, bf);   // pass-through field (write-once)

            #pragma unroll
            for (int c = 0; c < 8; c++) {
                float4 cc = ld4(xb + c * PLANE + rowc);    // staged this/last iter -> L1 hit
                float4 rv = ld_cs4(rb + c * PLANE + rowc); // read-once stream
                float4 o;
                o.x = flip_one(cc.x, J.x, bf.x, rv.x, d0);
                o.y = flip_one(cc.y, J.y, bf.y, rv.y, d1);
                o.z = flip_one(cc.z, J.z, bf.z, rv.z, d2);
                o.w = flip_one(cc.w, J.w, bf.w, rv.w, d3);
                st_cs4(ob + c * PLANE + rowc, o);          // write-once
            }
        }
    }
}

extern "C" void kernel_launch(void* const* d_in, const int* in_sizes, int n_in,
                              void* d_out, int out_size) {
    const float* x    = (const float*)d_in[0];   // (4,9,1024,1024)
    const float* rnd  = (const float*)d_in[1];   // (4,8,1024,1024)
    const float* drop = (const float*)d_in[2];   // (1024,1024)
    // d_in[3] = nn_kernel: fixed cross structure, baked into the kernel
    float* out = (float*)d_out;

    int grid = 4 * SPB;                          // 304 CTAs = 2/SM x 152 SMs, single wave
    ising_step_kernel<<<grid, 512>>>(x, rnd, drop, out);
}